// round 2
// baseline (speedup 1.0000x reference)
#include <cuda_runtime.h>
#include <cstdint>
#include <math_constants.h>

#define N_ANCHOR 589824      // (1024/4)^2 * 9
#define IMG 1024
#define JOINTS 16
#define NPRE 600
#define NPOST 6
#define NMS_T 0.7f
#define MINSZ 16.0f
#define NBINS 4096
#define CAP 8192

// ---------------- scratch (static __device__ globals; no runtime alloc) ----------------
__device__ float4   g_roi[N_ANCHOR];                 // clipped boxes
__device__ unsigned g_key[N_ANCHOR];                 // monotone rank key (0 = invalid)
__device__ unsigned g_hist[NBINS];
__device__ unsigned g_T;                             // threshold bin
__device__ unsigned g_cand_count;
__device__ unsigned long long g_cand[CAP];           // (key<<32) | ~idx
__device__ int      g_box6[NPOST * 4];               // int-cast kept boxes

// Monotone total-order mapping of float -> uint (ascending)
__device__ __forceinline__ unsigned rank_key(float d) {
    unsigned u = __float_as_uint(d);
    return (u & 0x80000000u) ? ~u : (u | 0x80000000u);
}

// ---------------- K0: zero scratch ----------------
__global__ void k_zero() {
    int i = blockIdx.x * blockDim.x + threadIdx.x;
    if (i < NBINS) g_hist[i] = 0u;
    if (i == 0) { g_cand_count = 0u; g_T = 0u; }
}

// ---------------- K1: per-anchor decode + key + histogram ----------------
__global__ void __launch_bounds__(512) k_compute(const float* __restrict__ shift,
                                                 const float* __restrict__ score,
                                                 const float* __restrict__ anchor) {
    __shared__ unsigned sh[NBINS];
    for (int i = threadIdx.x; i < NBINS; i += blockDim.x) sh[i] = 0u;
    __syncthreads();

    for (int i = blockIdx.x * blockDim.x + threadIdx.x; i < N_ANCHOR;
         i += gridDim.x * blockDim.x) {
        float4 a = ((const float4*)anchor)[i];
        float4 s = ((const float4*)shift)[i];
        float2 c = ((const float2*)score)[i];

        // ranking key: softmax fg is monotone in (c1 - c0)
        float d = c.y - c.x;

        float aw = a.z - a.x, ah = a.w - a.y;
        float ax = a.x + 0.5f * aw, ay = a.y + 0.5f * ah;
        float bx = ax + aw * s.x, by = ay + ah * s.y;
        float bw = aw * expf(s.z), bh = ah * expf(s.w);
        float x1 = bx - 0.5f * bw, y1 = by - 0.5f * bh;
        float x2 = bw + x1,        y2 = bh + y1;
        x1 = fminf(fmaxf(x1, 0.f), (float)IMG);
        y1 = fminf(fmaxf(y1, 0.f), (float)IMG);
        x2 = fminf(fmaxf(x2, 0.f), (float)IMG);
        y2 = fminf(fmaxf(y2, 0.f), (float)IMG);

        bool valid = ((x2 - x1) >= MINSZ) && ((y2 - y1) >= MINSZ);
        unsigned key = valid ? rank_key(d) : 0u;
        // key==0 for a valid box requires d == NaN; impossible here.

        g_roi[i] = make_float4(x1, y1, x2, y2);
        g_key[i] = key;
        atomicAdd(&sh[key >> 20], 1u);   // 4096 bins, key>>20 <= 4095
    }
    __syncthreads();
    for (int i = threadIdx.x; i < NBINS; i += blockDim.x)
        if (sh[i]) atomicAdd(&g_hist[i], sh[i]);
}

// ---------------- K2: find threshold bin (cum from top >= NPRE) ----------------
__global__ void k_thresh() {
    __shared__ unsigned h[NBINS];
    for (int i = threadIdx.x; i < NBINS; i += blockDim.x) h[i] = g_hist[i];
    __syncthreads();
    if (threadIdx.x == 0) {
        unsigned cum = 0; unsigned T = 0;
        for (int b = NBINS - 1; b >= 1; --b) {
            cum += h[b];
            if (cum >= NPRE) { T = (unsigned)b; break; }
        }
        g_T = T;
    }
}

// ---------------- K3: collect candidates with bin >= T ----------------
__global__ void __launch_bounds__(512) k_collect() {
    unsigned T = g_T;
    for (int i = blockIdx.x * blockDim.x + threadIdx.x; i < N_ANCHOR;
         i += gridDim.x * blockDim.x) {
        unsigned key = g_key[i];
        if (key != 0u && (key >> 20) >= T) {
            unsigned p = atomicAdd(&g_cand_count, 1u);
            if (p < CAP)
                g_cand[p] = ((unsigned long long)key << 32) |
                            (unsigned long long)(~(unsigned)i);
        }
    }
}

// ---------------- K4: single-block bitonic sort + greedy NMS (early exit @6) ----------------
__global__ void __launch_bounds__(1024) k_nms() {
    extern __shared__ unsigned long long srt[];
    __shared__ float4 box[NPRE];
    __shared__ float  area[NPRE];
    __shared__ unsigned char sup[NPRE];
    __shared__ int keeps[NPOST];

    const int tid = threadIdx.x;
    unsigned cnt = g_cand_count;
    if (cnt > CAP) cnt = CAP;

    unsigned n = 2;
    while (n < cnt) n <<= 1;

    for (unsigned i = tid; i < n; i += 1024)
        srt[i] = (i < cnt) ? g_cand[i] : 0ULL;
    __syncthreads();

    // bitonic sort, descending (key, ~idx): larger key first; ties -> smaller idx first
    for (unsigned k = 2; k <= n; k <<= 1) {
        for (unsigned j = k >> 1; j > 0; j >>= 1) {
            for (unsigned i = tid; i < n; i += 1024) {
                unsigned ixj = i ^ j;
                if (ixj > i) {
                    unsigned long long x = srt[i], y = srt[ixj];
                    bool desc = ((i & k) == 0);
                    if (desc ? (x < y) : (x > y)) { srt[i] = y; srt[ixj] = x; }
                }
            }
            __syncthreads();
        }
    }

    int ntop = (int)cnt; if (ntop > NPRE) ntop = NPRE;

    for (int i = tid; i < ntop; i += 1024) {
        unsigned idx = ~(unsigned)(srt[i] & 0xFFFFFFFFull);
        float4 b = g_roi[idx];
        box[i] = b;
        area[i] = (b.z - b.x) * (b.w - b.y);
        sup[i] = 0;
    }
    __syncthreads();

    // greedy NMS in score order; stop after 6 keeps (only first 6 matter downstream)
    int found = 0;
    for (int i = 0; i < ntop; ++i) {
        if (sup[i]) continue;                 // uniform read from shared
        if (tid == 0) keeps[found] = i;
        ++found;
        if (found >= NPOST) break;
        float4 bi = box[i];
        float ai = area[i];
        for (int jdx = i + 1 + tid; jdx < ntop; jdx += 1024) {
            float4 bj = box[jdx];
            float ix1 = fmaxf(bi.x, bj.x), iy1 = fmaxf(bi.y, bj.y);
            float ix2 = fminf(bi.z, bj.z), iy2 = fminf(bi.w, bj.w);
            float inter = fmaxf(ix2 - ix1, 0.f) * fmaxf(iy2 - iy1, 0.f);
            float iou = __fdiv_rn(inter, ai + area[jdx] - inter);
            if (iou > NMS_T) sup[jdx] = 1;
        }
        __syncthreads();
    }
    __syncthreads();

    if (tid < NPOST) {
        int src = (tid < found) ? keeps[tid] : ((ntop > 0) ? keeps[0] * 0 : 0); // fill_value=0 -> box[0]
        // reference: nonzero(keep, size=6, fill_value=0) -> index 0 of the sorted list
        if (tid >= found) src = 0;
        float4 b = (ntop > 0) ? box[src] : make_float4(0.f, 0.f, 0.f, 0.f);
        g_box6[tid * 4 + 0] = (int)b.x;
        g_box6[tid * 4 + 1] = (int)b.y;
        g_box6[tid * 4 + 2] = (int)b.z;
        g_box6[tid * 4 + 3] = (int)b.w;
    }
}

// ---------------- K5: per-(box,joint) ROI argmax + joint coords ----------------
__global__ void __launch_bounds__(256) k_joints(const float* __restrict__ hm,
                                                float* __restrict__ out) {
    const int b = blockIdx.x >> 4;
    const int j = blockIdx.x & 15;
    const int x0 = g_box6[b * 4 + 0], y0 = g_box6[b * 4 + 1];
    const int x1 = g_box6[b * 4 + 2], y1 = g_box6[b * 4 + 3];

    const float* H = hm + (size_t)j * IMG * IMG;
    float bv = -CUDART_INF_F;
    int bidx = 0x7fffffff;

    for (int gx = x0; gx < x1; ++gx) {
        const float* row = H + (size_t)gx * IMG;
        for (int gy = y0 + (int)threadIdx.x; gy < y1; gy += blockDim.x) {
            float v = row[gy];
            int gi = gx * IMG + gy;
            if (v > bv || (v == bv && gi < bidx)) { bv = v; bidx = gi; }
        }
    }

    __shared__ float sv[256];
    __shared__ int   si[256];
    sv[threadIdx.x] = bv; si[threadIdx.x] = bidx;
    __syncthreads();
    for (int s = 128; s > 0; s >>= 1) {
        if ((int)threadIdx.x < s) {
            float v = sv[threadIdx.x + s]; int gi = si[threadIdx.x + s];
            if (v > sv[threadIdx.x] ||
                (v == sv[threadIdx.x] && gi < si[threadIdx.x])) {
                sv[threadIdx.x] = v; si[threadIdx.x] = gi;
            }
        }
        __syncthreads();
    }

    if (threadIdx.x == 0) {
        int gi = si[0];
        int gx = gi / IMG, gy = gi % IMG;
        int local = (gx - x0) * (y1 - y0) + (gy - y0);
        float jx = floorf(__fdiv_rn((float)local, (float)(x1 - x0)));
        float jy = (float)(local % (y1 - y0));
        out[(b * JOINTS + j) * 2 + 0] = jx;
        out[(b * JOINTS + j) * 2 + 1] = jy;
    }
}

// ---------------- host launcher ----------------
extern "C" void kernel_launch(void* const* d_in, const int* in_sizes, int n_in,
                              void* d_out, int out_size) {
    const float* shift  = (const float*)d_in[0];
    const float* score  = (const float*)d_in[1];
    const float* hm     = (const float*)d_in[2];
    const float* anchor = (const float*)d_in[3];
    float* out = (float*)d_out;

    cudaFuncSetAttribute(k_nms, cudaFuncAttributeMaxDynamicSharedMemorySize,
                         CAP * (int)sizeof(unsigned long long));

    k_zero<<<(NBINS + 1023) / 1024, 1024>>>();
    k_compute<<<148, 512>>>(shift, score, anchor);
    k_thresh<<<1, 1024>>>();
    k_collect<<<148, 512>>>();
    k_nms<<<1, 1024, CAP * sizeof(unsigned long long)>>>();
    k_joints<<<NPOST * JOINTS, 256>>>(hm, out);
}

// round 3
// speedup vs baseline: 1.8099x; 1.8099x over previous
#include <cuda_runtime.h>
#include <cstdint>
#include <math_constants.h>

#define N_ANCHOR 589824      // (1024/4)^2 * 9
#define IMG 1024
#define JOINTS 16
#define NPRE 600
#define NPOST 6
#define NMS_T 0.7f
#define MINSZ 16.0f
#define NBINS 4096
#define CAP 8192
#define NSLICE 8

// ---------------- scratch (static __device__ globals) ----------------
__device__ unsigned g_key[N_ANCHOR];                 // monotone rank key (0 = invalid)
__device__ unsigned g_hist[NBINS];
__device__ unsigned g_T;
__device__ unsigned g_cand_count;
__device__ unsigned long long g_cand[CAP];           // (key<<32) | ~anchor_idx
__device__ float4   g_boxmap[N_ANCHOR];              // sparse: written only for candidates
__device__ int      g_box6[NPOST * 4];
__device__ unsigned long long g_jmax[NPOST * JOINTS];

// Monotone total-order mapping float -> uint (ascending)
__device__ __forceinline__ unsigned rank_key(float d) {
    unsigned u = __float_as_uint(d);
    return (u & 0x80000000u) ? ~u : (u | 0x80000000u);
}

__device__ __forceinline__ float4 decode_box(float4 a, float4 s) {
    float aw = a.z - a.x, ah = a.w - a.y;
    float ax = a.x + 0.5f * aw, ay = a.y + 0.5f * ah;
    float bx = ax + aw * s.x, by = ay + ah * s.y;
    float bw = aw * expf(s.z), bh = ah * expf(s.w);
    float x1 = bx - 0.5f * bw, y1 = by - 0.5f * bh;
    float x2 = bw + x1,        y2 = bh + y1;
    x1 = fminf(fmaxf(x1, 0.f), (float)IMG);
    y1 = fminf(fmaxf(y1, 0.f), (float)IMG);
    x2 = fminf(fmaxf(x2, 0.f), (float)IMG);
    y2 = fminf(fmaxf(y2, 0.f), (float)IMG);
    return make_float4(x1, y1, x2, y2);
}

// ---------------- K0: zero scratch ----------------
__global__ void k_zero() {
    int i = blockIdx.x * blockDim.x + threadIdx.x;
    if (i < NBINS) g_hist[i] = 0u;
    if (i < NPOST * JOINTS) g_jmax[i] = 0ULL;
    if (i == 0) { g_cand_count = 0u; g_T = 0u; }
}

// ---------------- K1: per-anchor key + histogram (no box store) ----------------
__global__ void __launch_bounds__(512) k_compute(const float* __restrict__ shift,
                                                 const float* __restrict__ score,
                                                 const float* __restrict__ anchor) {
    __shared__ unsigned sh[NBINS];
    for (int i = threadIdx.x; i < NBINS; i += blockDim.x) sh[i] = 0u;
    __syncthreads();

    for (int i = blockIdx.x * blockDim.x + threadIdx.x; i < N_ANCHOR;
         i += gridDim.x * blockDim.x) {
        float4 a = ((const float4*)anchor)[i];
        float4 s = ((const float4*)shift)[i];
        float2 c = ((const float2*)score)[i];

        float d = c.y - c.x;                 // softmax fg monotone in d
        float4 b = decode_box(a, s);
        bool valid = ((b.z - b.x) >= MINSZ) && ((b.w - b.y) >= MINSZ);
        unsigned key = valid ? rank_key(d) : 0u;

        g_key[i] = key;
        atomicAdd(&sh[key >> 20], 1u);
    }
    __syncthreads();
    for (int i = threadIdx.x; i < NBINS; i += blockDim.x)
        if (sh[i]) atomicAdd(&g_hist[i], sh[i]);
}

// ---------------- K2: parallel threshold-bin search ----------------
__global__ void __launch_bounds__(1024) k_thresh() {
    __shared__ unsigned part[1024];
    const int t = threadIdx.x;

    // chunk t covers offsets o = 4t..4t+3 from the top (bin = NBINS-1-o), bins >= 1 only
    unsigned s = 0;
    #pragma unroll
    for (int q = 0; q < 4; ++q) {
        int b = NBINS - 1 - (4 * t + q);
        if (b >= 1) s += g_hist[b];
    }
    part[t] = s;
    __syncthreads();

    // inclusive Hillis-Steele scan over 1024 chunks
    unsigned v = s;
    for (int off = 1; off < 1024; off <<= 1) {
        unsigned u = (t >= off) ? part[t - off] : 0u;
        __syncthreads();
        v += u; part[t] = v;
        __syncthreads();
    }

    unsigned inc = part[t];
    unsigned exc = (t == 0) ? 0u : part[t - 1];
    if (exc < NPRE && inc >= NPRE) {
        unsigned cum = exc;
        #pragma unroll
        for (int q = 0; q < 4; ++q) {
            int b = NBINS - 1 - (4 * t + q);
            if (b >= 1) {
                cum += g_hist[b];
                if (cum >= NPRE) { g_T = (unsigned)b; break; }
            }
        }
    }
    // if total < NPRE: no crossing, g_T stays 0 (all valid keys collected)
}

// ---------------- K3: vectorized collect + candidate box recompute ----------------
__global__ void __launch_bounds__(512) k_collect(const float* __restrict__ shift,
                                                 const float* __restrict__ score,
                                                 const float* __restrict__ anchor) {
    const unsigned T = g_T;
    int i4 = blockIdx.x * blockDim.x + threadIdx.x;   // exactly N_ANCHOR/4 threads
    uint4 k4 = ((const uint4*)g_key)[i4];

    #pragma unroll
    for (int q = 0; q < 4; ++q) {
        unsigned key = (q == 0) ? k4.x : (q == 1) ? k4.y : (q == 2) ? k4.z : k4.w;
        if (key != 0u && (key >> 20) >= T) {
            int i = i4 * 4 + q;
            float4 a = ((const float4*)anchor)[i];
            float4 s = ((const float4*)shift)[i];
            g_boxmap[i] = decode_box(a, s);
            unsigned p = atomicAdd(&g_cand_count, 1u);
            if (p < CAP)
                g_cand[p] = ((unsigned long long)key << 32) |
                            (unsigned long long)(~(unsigned)i);
        }
    }
}

// ---------------- K4: bitonic sort + greedy NMS (early exit @6) ----------------
__global__ void __launch_bounds__(1024) k_nms() {
    extern __shared__ unsigned long long srt[];
    __shared__ float4 box[NPRE];
    __shared__ float  area[NPRE];
    __shared__ unsigned char sup[NPRE];
    __shared__ int keeps[NPOST];

    const int tid = threadIdx.x;
    unsigned cnt = g_cand_count;
    if (cnt > CAP) cnt = CAP;

    unsigned n = 2;
    while (n < cnt) n <<= 1;

    for (unsigned i = tid; i < n; i += 1024)
        srt[i] = (i < cnt) ? g_cand[i] : 0ULL;
    __syncthreads();

    for (unsigned k = 2; k <= n; k <<= 1) {
        for (unsigned j = k >> 1; j > 0; j >>= 1) {
            for (unsigned i = tid; i < n; i += 1024) {
                unsigned ixj = i ^ j;
                if (ixj > i) {
                    unsigned long long x = srt[i], y = srt[ixj];
                    bool desc = ((i & k) == 0);
                    if (desc ? (x < y) : (x > y)) { srt[i] = y; srt[ixj] = x; }
                }
            }
            __syncthreads();
        }
    }

    int ntop = (int)cnt; if (ntop > NPRE) ntop = NPRE;

    for (int i = tid; i < ntop; i += 1024) {
        unsigned idx = ~(unsigned)(srt[i] & 0xFFFFFFFFull);
        float4 b = g_boxmap[idx];
        box[i] = b;
        area[i] = (b.z - b.x) * (b.w - b.y);
        sup[i] = 0;
    }
    __syncthreads();

    int found = 0;
    for (int i = 0; i < ntop; ++i) {
        if (sup[i]) continue;
        if (tid == 0) keeps[found] = i;
        ++found;
        if (found >= NPOST) break;
        float4 bi = box[i];
        float ai = area[i];
        for (int jdx = i + 1 + tid; jdx < ntop; jdx += 1024) {
            float4 bj = box[jdx];
            float ix1 = fmaxf(bi.x, bj.x), iy1 = fmaxf(bi.y, bj.y);
            float ix2 = fminf(bi.z, bj.z), iy2 = fminf(bi.w, bj.w);
            float inter = fmaxf(ix2 - ix1, 0.f) * fmaxf(iy2 - iy1, 0.f);
            float iou = __fdiv_rn(inter, ai + area[jdx] - inter);
            if (iou > NMS_T) sup[jdx] = 1;
        }
        __syncthreads();
    }
    __syncthreads();

    if (tid < NPOST) {
        int src = (tid < found) ? keeps[tid] : 0;   // fill_value=0 -> sorted box[0]
        float4 b = (ntop > 0) ? box[src] : make_float4(0.f, 0.f, 0.f, 0.f);
        g_box6[tid * 4 + 0] = (int)b.x;
        g_box6[tid * 4 + 1] = (int)b.y;
        g_box6[tid * 4 + 2] = (int)b.z;
        g_box6[tid * 4 + 3] = (int)b.w;
    }
}

// ---------------- K5: sliced ROI argmax via packed atomicMax ----------------
__global__ void __launch_bounds__(256) k_joints(const float* __restrict__ hm) {
    const int slice = blockIdx.x & (NSLICE - 1);
    const int bj = blockIdx.x >> 3;            // 0..95
    const int b = bj >> 4, j = bj & 15;

    const int x0 = g_box6[b * 4 + 0], y0 = g_box6[b * 4 + 1];
    const int x1 = g_box6[b * 4 + 2], y1 = g_box6[b * 4 + 3];
    const int cols = y1 - y0;
    const int total = (x1 - x0) * cols;
    const int start = (int)((long long)slice * total / NSLICE);
    const int end   = (int)((long long)(slice + 1) * total / NSLICE);

    const float* H = hm + (size_t)j * IMG * IMG;

    unsigned long long best = 0ULL;
    for (int f = start + (int)threadIdx.x; f < end; f += 256) {
        int gx = x0 + f / cols;
        int gy = y0 + f % cols;
        float v = H[gx * IMG + gy];
        int gi = gx * IMG + gy;
        unsigned long long pk = ((unsigned long long)rank_key(v) << 32) |
                                (unsigned long long)(~(unsigned)gi);
        best = (pk > best) ? pk : best;
    }

    __shared__ unsigned long long red[256];
    red[threadIdx.x] = best;
    __syncthreads();
    for (int s = 128; s > 0; s >>= 1) {
        if ((int)threadIdx.x < s) {
            unsigned long long o = red[threadIdx.x + s];
            if (o > red[threadIdx.x]) red[threadIdx.x] = o;
        }
        __syncthreads();
    }
    if (threadIdx.x == 0 && red[0] != 0ULL)
        atomicMax(&g_jmax[bj], red[0]);
}

// ---------------- K6: finalize joint coords ----------------
__global__ void k_final(float* __restrict__ out) {
    int t = threadIdx.x;
    if (t >= NPOST * JOINTS) return;
    int b = t >> 4;
    const int x0 = g_box6[b * 4 + 0], y0 = g_box6[b * 4 + 1];
    const int x1 = g_box6[b * 4 + 2], y1 = g_box6[b * 4 + 3];

    unsigned gi = ~(unsigned)(g_jmax[t] & 0xFFFFFFFFull);
    int gx = (int)gi / IMG, gy = (int)gi % IMG;
    int local = (gx - x0) * (y1 - y0) + (gy - y0);
    float jx = floorf(__fdiv_rn((float)local, (float)(x1 - x0)));
    float jy = (float)(local % (y1 - y0));
    out[t * 2 + 0] = jx;
    out[t * 2 + 1] = jy;
}

// ---------------- host launcher ----------------
extern "C" void kernel_launch(void* const* d_in, const int* in_sizes, int n_in,
                              void* d_out, int out_size) {
    const float* shift  = (const float*)d_in[0];
    const float* score  = (const float*)d_in[1];
    const float* hm     = (const float*)d_in[2];
    const float* anchor = (const float*)d_in[3];
    float* out = (float*)d_out;

    cudaFuncSetAttribute(k_nms, cudaFuncAttributeMaxDynamicSharedMemorySize,
                         CAP * (int)sizeof(unsigned long long));

    k_zero<<<4, 1024>>>();
    k_compute<<<296, 512>>>(shift, score, anchor);
    k_thresh<<<1, 1024>>>();
    k_collect<<<N_ANCHOR / 4 / 512, 512>>>(shift, score, anchor);
    k_nms<<<1, 1024, CAP * sizeof(unsigned long long)>>>();
    k_joints<<<NPOST * JOINTS * NSLICE, 256>>>(hm);
    k_final<<<1, 128>>>(out);
}